// round 1
// baseline (speedup 1.0000x reference)
#include <cuda_runtime.h>

typedef unsigned long long u64t;

__device__ __forceinline__ u64t fma2(u64t a, u64t b, u64t c) {
    u64t d;
    asm("fma.rn.f32x2 %0, %1, %2, %3;" : "=l"(d) : "l"(a), "l"(b), "l"(c));
    return d;
}
__device__ __forceinline__ u64t pk2(float lo, float hi) {
    u64t d;
    asm("mov.b64 %0, {%1, %2};" : "=l"(d) : "f"(lo), "f"(hi));
    return d;
}
__device__ __forceinline__ void unpk(u64t v, float& lo, float& hi) {
    asm("mov.b64 {%0, %1}, %2;" : "=f"(lo), "=f"(hi) : "l"(v));
}

// ---- shared memory layout (u64t units, each entry = duplicated (w,w) pair) ----
// sW1t: [24][19][20]  W1t[j][k][r] = W1[j][r][k]   (r padded 19->20 for LDS.128)
// sW2t: [24][19][6]   W2t[j][k][d] = W2[j][d][k]
// sW0t: [288][6]      W0t[k][d]    = W0[d][k]
// sB1 : [24][20]      (padded)
// sB2 : [24][6]
// sB0 : [6]
#define OW1 0
#define OW2 9120
#define OW0 11856
#define OB1 13584
#define OB2 14064
#define OB0 14208
#define SM_U64 14214   // 113712 bytes

// per-joint worker. J = joint, PS = parent's slot (-1 for root), WS = slot to write.
template<int J, int PS, int WS>
__device__ __forceinline__ void do_joint(
    const float* __restrict__ r0, const float* __restrict__ t0,
    float* __restrict__ ob, const u64t* __restrict__ sm,
    u64t (&fslot)[4][6], u64t (&jslot)[4][3], const u64t (&g)[6])
{
    // load rot (9) and jtr (3) for both packed elements
    float ra[9], rb[9];
#pragma unroll
    for (int i = 0; i < 9; ++i) { ra[i] = r0[J*9 + i]; rb[i] = r0[216 + J*9 + i]; }
    float ja[3], jb[3];
#pragma unroll
    for (int i = 0; i < 3; ++i) { ja[i] = t0[J*3 + i]; jb[i] = t0[72 + J*3 + i]; }

    float bla, blb;
    if (PS < 0) {
        bla = sqrtf(ja[0]*ja[0] + ja[1]*ja[1] + ja[2]*ja[2]);
        blb = sqrtf(jb[0]*jb[0] + jb[1]*jb[1] + jb[2]*jb[2]);
    } else {
        float da0, da1, da2, db0, db1, db2;
        {
            float pa, pb;
            unpk(jslot[PS < 0 ? 0 : PS][0], pa, pb); da0 = ja[0] - pa; db0 = jb[0] - pb;
            unpk(jslot[PS < 0 ? 0 : PS][1], pa, pb); da1 = ja[1] - pa; db1 = jb[1] - pb;
            unpk(jslot[PS < 0 ? 0 : PS][2], pa, pb); da2 = ja[2] - pa; db2 = jb[2] - pb;
        }
        bla = sqrtf(da0*da0 + da1*da1 + da2*da2);
        blb = sqrtf(db0*db0 + db1*db1 + db2*db2);
    }

    // x = [rot(9), jtr(3), bone(1), feat(6)]
    u64t x[19];
#pragma unroll
    for (int i = 0; i < 9; ++i) x[i] = pk2(ra[i], rb[i]);
#pragma unroll
    for (int i = 0; i < 3; ++i) { x[9 + i] = pk2(ja[i], jb[i]); jslot[WS][i] = x[9 + i]; }
    x[12] = pk2(bla, blb);
#pragma unroll
    for (int i = 0; i < 6; ++i) x[13 + i] = (PS < 0) ? g[i] : fslot[PS < 0 ? 0 : PS][i];

    // layer 1: h = relu(W1[j] @ x + b1[j])   (k-outer, 19 parallel accumulators + 1 pad)
    u64t h[20];
    {
        const ulonglong2* bb = (const ulonglong2*)(sm + OB1 + J*20);
#pragma unroll
        for (int r = 0; r < 10; ++r) { ulonglong2 t = bb[r]; h[2*r] = t.x; h[2*r+1] = t.y; }
    }
#pragma unroll
    for (int k = 0; k < 19; ++k) {
        u64t xk = x[k];
        const ulonglong2* wr = (const ulonglong2*)(sm + OW1 + (J*19 + k)*20);
#pragma unroll
        for (int r = 0; r < 10; ++r) {
            ulonglong2 w = wr[r];
            h[2*r]   = fma2(xk, w.x, h[2*r]);
            h[2*r+1] = fma2(xk, w.y, h[2*r+1]);
        }
    }
#pragma unroll
    for (int r = 0; r < 19; ++r) {
        float a, b; unpk(h[r], a, b);
        h[r] = pk2(fmaxf(a, 0.f), fmaxf(b, 0.f));
    }

    // layer 2: o = W2[j] @ h + b2[j]
    u64t o[6];
    {
        const ulonglong2* bb = (const ulonglong2*)(sm + OB2 + J*6);
#pragma unroll
        for (int r = 0; r < 3; ++r) { ulonglong2 t = bb[r]; o[2*r] = t.x; o[2*r+1] = t.y; }
    }
#pragma unroll
    for (int k = 0; k < 19; ++k) {
        u64t hk = h[k];
        const ulonglong2* wr = (const ulonglong2*)(sm + OW2 + (J*19 + k)*6);
#pragma unroll
        for (int r = 0; r < 3; ++r) {
            ulonglong2 w = wr[r];
            o[2*r]   = fma2(hk, w.x, o[2*r]);
            o[2*r+1] = fma2(hk, w.y, o[2*r+1]);
        }
    }

    // keep feature for children + write both elements' 6 outputs
    float la[6], lb[6];
#pragma unroll
    for (int i = 0; i < 6; ++i) { fslot[WS][i] = o[i]; unpk(o[i], la[i], lb[i]); }
    float2* oa = (float2*)(ob + J*6);
    float2* obp = (float2*)(ob + 144 + J*6);
    oa[0]  = make_float2(la[0], la[1]); oa[1]  = make_float2(la[2], la[3]); oa[2]  = make_float2(la[4], la[5]);
    obp[0] = make_float2(lb[0], lb[1]); obp[1] = make_float2(lb[2], lb[3]); obp[2] = make_float2(lb[4], lb[5]);
}

__global__ void __launch_bounds__(128, 2)
pose_kernel(const float* __restrict__ rots, const float* __restrict__ jtrs,
            const float* __restrict__ W0, const float* __restrict__ b0,
            const float* __restrict__ W1, const float* __restrict__ b1,
            const float* __restrict__ W2, const float* __restrict__ b2,
            float* __restrict__ out, int pairs)
{
    extern __shared__ u64t sm[];
    const int tid = threadIdx.x;

    // ---- prologue: duplicate weights into smem as (w,w) pairs ----
    for (int i = tid; i < 24*19*20; i += 128) {
        int r = i % 20; int jk = i / 20; int k = jk % 19; int j = jk / 19;
        float w = (r < 19) ? W1[(j*19 + r)*19 + k] : 0.f;
        sm[OW1 + i] = pk2(w, w);
    }
    for (int i = tid; i < 24*19*6; i += 128) {
        int d = i % 6; int jk = i / 6; int k = jk % 19; int j = jk / 19;
        float w = W2[(j*6 + d)*19 + k];
        sm[OW2 + i] = pk2(w, w);
    }
    for (int i = tid; i < 288*6; i += 128) {
        int d = i % 6; int k = i / 6;
        float w = W0[d*288 + k];
        sm[OW0 + i] = pk2(w, w);
    }
    for (int i = tid; i < 24*20; i += 128) {
        int r = i % 20; int j = i / 20;
        float v = (r < 19) ? b1[j*19 + r] : 0.f;
        sm[OB1 + i] = pk2(v, v);
    }
    for (int i = tid; i < 24*6; i += 128) sm[OB2 + i] = pk2(b2[i], b2[i]);
    if (tid < 6) sm[OB0 + tid] = pk2(b0[tid], b0[tid]);
    __syncthreads();

    int p = blockIdx.x * 128 + tid;
    if (p >= pairs) return;

    const float* r0 = rots + (size_t)p * 432;   // elements 2p and 2p+1 (216 floats each)
    const float* t0 = jtrs + (size_t)p * 144;   // 72 floats each
    float* ob = out + (size_t)p * 288;          // 144 floats each

    // ---- pass 1: gfeat = W0 @ [rots_flat; jtrs_flat] + b0 ----
    u64t g[6];
#pragma unroll
    for (int d = 0; d < 6; ++d) g[d] = sm[OB0 + d];
    {
        const float4* a4 = (const float4*)r0;
        const float4* b4 = (const float4*)(r0 + 216);
#pragma unroll 6
        for (int q = 0; q < 54; ++q) {
            float4 A = a4[q], Bv = b4[q];
            float av[4] = {A.x, A.y, A.z, A.w};
            float bv[4] = {Bv.x, Bv.y, Bv.z, Bv.w};
#pragma unroll
            for (int c = 0; c < 4; ++c) {
                u64t xk = pk2(av[c], bv[c]);
                const ulonglong2* wr = (const ulonglong2*)(sm + OW0 + (q*4 + c)*6);
#pragma unroll
                for (int r = 0; r < 3; ++r) {
                    ulonglong2 w = wr[r];
                    g[2*r]   = fma2(xk, w.x, g[2*r]);
                    g[2*r+1] = fma2(xk, w.y, g[2*r+1]);
                }
            }
        }
        const float4* c4 = (const float4*)t0;
        const float4* d4 = (const float4*)(t0 + 72);
#pragma unroll 6
        for (int q = 0; q < 18; ++q) {
            float4 A = c4[q], Bv = d4[q];
            float av[4] = {A.x, A.y, A.z, A.w};
            float bv[4] = {Bv.x, Bv.y, Bv.z, Bv.w};
#pragma unroll
            for (int c = 0; c < 4; ++c) {
                u64t xk = pk2(av[c], bv[c]);
                const ulonglong2* wr = (const ulonglong2*)(sm + OW0 + (216 + q*4 + c)*6);
#pragma unroll
                for (int r = 0; r < 3; ++r) {
                    ulonglong2 w = wr[r];
                    g[2*r]   = fma2(xk, w.x, g[2*r]);
                    g[2*r+1] = fma2(xk, w.y, g[2*r+1]);
                }
            }
        }
    }

    // ---- pass 2: joint chain, 4-slot register liveness for parent feat/jtr ----
    u64t fslot[4][6];
    u64t jslot[4][3];

    do_joint< 0,-1,0>(r0, t0, ob, sm, fslot, jslot, g);
    do_joint< 1, 0,1>(r0, t0, ob, sm, fslot, jslot, g);
    do_joint< 2, 0,2>(r0, t0, ob, sm, fslot, jslot, g);
    do_joint< 3, 0,3>(r0, t0, ob, sm, fslot, jslot, g);
    do_joint< 4, 1,0>(r0, t0, ob, sm, fslot, jslot, g);
    do_joint< 5, 2,1>(r0, t0, ob, sm, fslot, jslot, g);
    do_joint< 6, 3,2>(r0, t0, ob, sm, fslot, jslot, g);
    do_joint< 7, 0,3>(r0, t0, ob, sm, fslot, jslot, g);
    do_joint< 8, 1,0>(r0, t0, ob, sm, fslot, jslot, g);
    do_joint< 9, 2,1>(r0, t0, ob, sm, fslot, jslot, g);
    do_joint<10, 3,2>(r0, t0, ob, sm, fslot, jslot, g);
    do_joint<11, 0,2>(r0, t0, ob, sm, fslot, jslot, g);
    do_joint<12, 1,2>(r0, t0, ob, sm, fslot, jslot, g);
    do_joint<13, 1,0>(r0, t0, ob, sm, fslot, jslot, g);
    do_joint<14, 1,3>(r0, t0, ob, sm, fslot, jslot, g);
    do_joint<15, 2,1>(r0, t0, ob, sm, fslot, jslot, g);
    do_joint<16, 0,1>(r0, t0, ob, sm, fslot, jslot, g);
    do_joint<17, 3,0>(r0, t0, ob, sm, fslot, jslot, g);
    do_joint<18, 1,3>(r0, t0, ob, sm, fslot, jslot, g);
    do_joint<19, 0,1>(r0, t0, ob, sm, fslot, jslot, g);
    do_joint<20, 3,0>(r0, t0, ob, sm, fslot, jslot, g);
    do_joint<21, 1,3>(r0, t0, ob, sm, fslot, jslot, g);
    do_joint<22, 0,1>(r0, t0, ob, sm, fslot, jslot, g);
    do_joint<23, 3,0>(r0, t0, ob, sm, fslot, jslot, g);
}

extern "C" void kernel_launch(void* const* d_in, const int* in_sizes, int n_in,
                              void* d_out, int out_size) {
    (void)n_in; (void)out_size;
    const float* rots = (const float*)d_in[0];
    const float* jtrs = (const float*)d_in[1];
    const float* W0   = (const float*)d_in[2];
    const float* b0   = (const float*)d_in[3];
    const float* W1   = (const float*)d_in[4];
    const float* b1   = (const float*)d_in[5];
    const float* W2   = (const float*)d_in[6];
    const float* b2   = (const float*)d_in[7];
    float* out = (float*)d_out;

    int B = in_sizes[0] / 216;        // rots is (B, 24, 9)
    int pairs = B / 2;
    int grid = (pairs + 127) / 128;
    size_t smem = (size_t)SM_U64 * sizeof(u64t);

    cudaFuncSetAttribute(pose_kernel, cudaFuncAttributeMaxDynamicSharedMemorySize, (int)smem);
    pose_kernel<<<grid, 128, smem>>>(rots, jtrs, W0, b0, W1, b1, W2, b2, out, pairs);
}

// round 3
// speedup vs baseline: 1.4205x; 1.4205x over previous
#include <cuda_runtime.h>

typedef unsigned long long u64t;

__device__ __forceinline__ u64t fma2(u64t a, u64t b, u64t c) {
    u64t d;
    asm("fma.rn.f32x2 %0, %1, %2, %3;" : "=l"(d) : "l"(a), "l"(b), "l"(c));
    return d;
}
__device__ __forceinline__ u64t pk2(float lo, float hi) {
    u64t d;
    asm("mov.b64 %0, {%1, %2};" : "=l"(d) : "f"(lo), "f"(hi));
    return d;
}
__device__ __forceinline__ void unpk(u64t v, float& lo, float& hi) {
    asm("mov.b64 {%0, %1}, %2;" : "=f"(lo), "=f"(hi) : "l"(v));
}
__device__ __forceinline__ float fsqrt_ap(float x) {
    float y;
    asm("sqrt.approx.f32 %0, %1;" : "=f"(y) : "f"(x));
    return y;
}

// ---- shared layout (u64t units). Each u64 = (w[2p], w[2p+1]) ROW pair, NOT duplicated ----
// sW1: [24][19 k][10 rp]   (row pair rp covers rows 2rp,2rp+1; rp=9 hi = 0 pad)   4560
// sW2: [24][20 k][3 dp]    (k=19 row holds b2 pairs; fed by h[19]=1)              1440
// sW0: [288 k][3 dp]                                                               864
// sB1: [24][10 rp]                                                                 240
// sB0: [3 dp]                                                                        3
#define OW1 0
#define OW2 4560
#define OW0 6000
#define OB1 6864
#define OB0 7104
#define SM_U64 7107   // 56856 bytes (<= 57344 for 4 CTAs/SM)

template<int J, int PS, int WS>
__device__ __forceinline__ void do_joint(
    const float* __restrict__ r0, const float* __restrict__ t0,
    float* __restrict__ ob, const u64t* __restrict__ sm,
    u64t (&fslot)[4][3], float (&jx)[4], float (&jy)[4], float (&jz)[4],
    const u64t (&g)[3])
{
    float xs[20];
#pragma unroll
    for (int i = 0; i < 9; ++i) xs[i] = r0[J*9 + i];
    float jxv = t0[J*3 + 0], jyv = t0[J*3 + 1], jzv = t0[J*3 + 2];
    xs[9] = jxv; xs[10] = jyv; xs[11] = jzv;

    float dx, dy, dz;
    if (PS < 0) { dx = jxv; dy = jyv; dz = jzv; }
    else {
        const int P = (PS < 0) ? 0 : PS;
        dx = jxv - jx[P]; dy = jyv - jy[P]; dz = jzv - jz[P];
    }
    xs[12] = fsqrt_ap(dx*dx + dy*dy + dz*dz);
    jx[WS] = jxv; jy[WS] = jyv; jz[WS] = jzv;

    if (PS < 0) {
        unpk(g[0], xs[13], xs[14]); unpk(g[1], xs[15], xs[16]); unpk(g[2], xs[17], xs[18]);
    } else {
        const int P = (PS < 0) ? 0 : PS;
        unpk(fslot[P][0], xs[13], xs[14]);
        unpk(fslot[P][1], xs[15], xs[16]);
        unpk(fslot[P][2], xs[17], xs[18]);
    }
    xs[19] = 0.f;

    // layer 1: h (10 row-pairs) = W1[j] @ x + b1[j]
    u64t h[10];
    {
        const ulonglong2* bb = (const ulonglong2*)(sm + OB1 + J*10);
#pragma unroll
        for (int r = 0; r < 5; ++r) { ulonglong2 t = bb[r]; h[2*r] = t.x; h[2*r+1] = t.y; }
    }
#pragma unroll
    for (int k = 0; k < 19; ++k) {
        u64t xx = pk2(xs[k], xs[k]);
        const ulonglong2* wr = (const ulonglong2*)(sm + OW1 + (J*19 + k)*10);
#pragma unroll
        for (int r = 0; r < 5; ++r) {
            ulonglong2 w = wr[r];
            h[2*r]   = fma2(xx, w.x, h[2*r]);
            h[2*r+1] = fma2(xx, w.y, h[2*r+1]);
        }
    }

    // relu -> scalars, hs[19] := 1 (feeds b2 row of sW2)
    float hs[20];
#pragma unroll
    for (int r = 0; r < 10; ++r) {
        float a, b; unpk(h[r], a, b);
        hs[2*r]   = fmaxf(a, 0.f);
        hs[2*r+1] = fmaxf(b, 0.f);
    }
    hs[19] = 1.0f;

    // layer 2: o (3 d-pairs) = W2[j] @ h  (+ b2 via k=19 row)
    u64t o[3];
    o[0] = 0ull; o[1] = 0ull; o[2] = 0ull;
#pragma unroll
    for (int kp = 0; kp < 10; ++kp) {
        const int k0 = 2*kp;
        const ulonglong2* wp = (const ulonglong2*)(sm + OW2 + (J*20 + k0)*3);
        ulonglong2 p0 = wp[0], p1 = wp[1], p2 = wp[2];
        u64t x0 = pk2(hs[k0], hs[k0]);
        u64t x1 = pk2(hs[k0+1], hs[k0+1]);
        o[0] = fma2(x0, p0.x, o[0]);
        o[1] = fma2(x0, p0.y, o[1]);
        o[2] = fma2(x0, p1.x, o[2]);
        o[0] = fma2(x1, p1.y, o[0]);
        o[1] = fma2(x1, p2.x, o[1]);
        o[2] = fma2(x1, p2.y, o[2]);
    }

    fslot[WS][0] = o[0]; fslot[WS][1] = o[1]; fslot[WS][2] = o[2];
    u64t* ow = (u64t*)(ob + J*6);
    ow[0] = o[0]; ow[1] = o[1]; ow[2] = o[2];
}

__global__ void __launch_bounds__(128, 4)
pose_kernel(const float* __restrict__ rots, const float* __restrict__ jtrs,
            const float* __restrict__ W0, const float* __restrict__ b0,
            const float* __restrict__ W1, const float* __restrict__ b1,
            const float* __restrict__ W2, const float* __restrict__ b2,
            float* __restrict__ out, int n)
{
    extern __shared__ u64t sm[];
    const int tid = threadIdx.x;

    // ---- prologue: pack weights as row-pairs (no duplication) ----
    for (int i = tid; i < 24*19*10; i += 128) {
        int rp = i % 10; int t = i / 10; int k = t % 19; int j = t / 19;
        int r = 2*rp;
        float lo = W1[(j*19 + r)*19 + k];
        float hi = (r + 1 < 19) ? W1[(j*19 + r + 1)*19 + k] : 0.f;
        sm[OW1 + i] = pk2(lo, hi);
    }
    for (int i = tid; i < 24*20*3; i += 128) {
        int dp = i % 3; int t = i / 3; int k = t % 20; int j = t / 20;
        float lo, hi;
        if (k < 19) { lo = W2[(j*6 + 2*dp)*19 + k]; hi = W2[(j*6 + 2*dp + 1)*19 + k]; }
        else        { lo = b2[j*6 + 2*dp];          hi = b2[j*6 + 2*dp + 1]; }
        sm[OW2 + i] = pk2(lo, hi);
    }
    for (int i = tid; i < 288*3; i += 128) {
        int dp = i % 3; int k = i / 3;
        sm[OW0 + i] = pk2(W0[(2*dp)*288 + k], W0[(2*dp + 1)*288 + k]);
    }
    for (int i = tid; i < 24*10; i += 128) {
        int rp = i % 10; int j = i / 10;
        int r = 2*rp;
        float lo = b1[j*19 + r];
        float hi = (r + 1 < 19) ? b1[j*19 + r + 1] : 0.f;
        sm[OB1 + i] = pk2(lo, hi);
    }
    if (tid < 3) sm[OB0 + tid] = pk2(b0[2*tid], b0[2*tid + 1]);
    __syncthreads();

    int e = blockIdx.x * 128 + tid;
    if (e >= n) return;

    const float* r0 = rots + (size_t)e * 216;
    const float* t0 = jtrs + (size_t)e * 72;
    float* ob = out + (size_t)e * 144;

    // ---- pass 1: gfeat = W0 @ [rot_flat; jtr_flat] + b0, d-pairs ----
    u64t g[3];
    g[0] = sm[OB0 + 0]; g[1] = sm[OB0 + 1]; g[2] = sm[OB0 + 2];

    {
        const float4* a4 = (const float4*)r0;
#pragma unroll 6
        for (int q = 0; q < 54; ++q) {
            float4 A = a4[q];
            float v[4] = {A.x, A.y, A.z, A.w};
#pragma unroll
            for (int cp = 0; cp < 2; ++cp) {
                int k0 = 4*q + 2*cp;
                const ulonglong2* wp = (const ulonglong2*)(sm + OW0 + k0*3);
                ulonglong2 p0 = wp[0], p1 = wp[1], p2 = wp[2];
                u64t x0 = pk2(v[2*cp],   v[2*cp]);
                u64t x1 = pk2(v[2*cp+1], v[2*cp+1]);
                g[0] = fma2(x0, p0.x, g[0]);
                g[1] = fma2(x0, p0.y, g[1]);
                g[2] = fma2(x0, p1.x, g[2]);
                g[0] = fma2(x1, p1.y, g[0]);
                g[1] = fma2(x1, p2.x, g[1]);
                g[2] = fma2(x1, p2.y, g[2]);
            }
        }
        const float4* c4 = (const float4*)t0;
#pragma unroll 6
        for (int q = 0; q < 18; ++q) {
            float4 A = c4[q];
            float v[4] = {A.x, A.y, A.z, A.w};
#pragma unroll
            for (int cp = 0; cp < 2; ++cp) {
                int k0 = 216 + 4*q + 2*cp;
                const ulonglong2* wp = (const ulonglong2*)(sm + OW0 + k0*3);
                ulonglong2 p0 = wp[0], p1 = wp[1], p2 = wp[2];
                u64t x0 = pk2(v[2*cp],   v[2*cp]);
                u64t x1 = pk2(v[2*cp+1], v[2*cp+1]);
                g[0] = fma2(x0, p0.x, g[0]);
                g[1] = fma2(x0, p0.y, g[1]);
                g[2] = fma2(x0, p1.x, g[2]);
                g[0] = fma2(x1, p1.y, g[0]);
                g[1] = fma2(x1, p2.x, g[1]);
                g[2] = fma2(x1, p2.y, g[2]);
            }
        }
    }

    // ---- pass 2: joint chain, 4-slot liveness allocation ----
    u64t fslot[4][3];
    float jx[4], jy[4], jz[4];

    do_joint< 0,-1,0>(r0, t0, ob, sm, fslot, jx, jy, jz, g);
    do_joint< 1, 0,1>(r0, t0, ob, sm, fslot, jx, jy, jz, g);
    do_joint< 2, 0,2>(r0, t0, ob, sm, fslot, jx, jy, jz, g);
    do_joint< 3, 0,3>(r0, t0, ob, sm, fslot, jx, jy, jz, g);
    do_joint< 4, 1,0>(r0, t0, ob, sm, fslot, jx, jy, jz, g);
    do_joint< 5, 2,1>(r0, t0, ob, sm, fslot, jx, jy, jz, g);
    do_joint< 6, 3,2>(r0, t0, ob, sm, fslot, jx, jy, jz, g);
    do_joint< 7, 0,3>(r0, t0, ob, sm, fslot, jx, jy, jz, g);
    do_joint< 8, 1,0>(r0, t0, ob, sm, fslot, jx, jy, jz, g);
    do_joint< 9, 2,1>(r0, t0, ob, sm, fslot, jx, jy, jz, g);
    do_joint<10, 3,2>(r0, t0, ob, sm, fslot, jx, jy, jz, g);
    do_joint<11, 0,2>(r0, t0, ob, sm, fslot, jx, jy, jz, g);
    do_joint<12, 1,2>(r0, t0, ob, sm, fslot, jx, jy, jz, g);
    do_joint<13, 1,0>(r0, t0, ob, sm, fslot, jx, jy, jz, g);
    do_joint<14, 1,3>(r0, t0, ob, sm, fslot, jx, jy, jz, g);
    do_joint<15, 2,1>(r0, t0, ob, sm, fslot, jx, jy, jz, g);
    do_joint<16, 0,1>(r0, t0, ob, sm, fslot, jx, jy, jz, g);
    do_joint<17, 3,0>(r0, t0, ob, sm, fslot, jx, jy, jz, g);
    do_joint<18, 1,3>(r0, t0, ob, sm, fslot, jx, jy, jz, g);
    do_joint<19, 0,1>(r0, t0, ob, sm, fslot, jx, jy, jz, g);
    do_joint<20, 3,0>(r0, t0, ob, sm, fslot, jx, jy, jz, g);
    do_joint<21, 1,3>(r0, t0, ob, sm, fslot, jx, jy, jz, g);
    do_joint<22, 0,1>(r0, t0, ob, sm, fslot, jx, jy, jz, g);
    do_joint<23, 3,0>(r0, t0, ob, sm, fslot, jx, jy, jz, g);
}

extern "C" void kernel_launch(void* const* d_in, const int* in_sizes, int n_in,
                              void* d_out, int out_size) {
    (void)n_in; (void)out_size;
    const float* rots = (const float*)d_in[0];
    const float* jtrs = (const float*)d_in[1];
    const float* W0   = (const float*)d_in[2];
    const float* b0   = (const float*)d_in[3];
    const float* W1   = (const float*)d_in[4];
    const float* b1   = (const float*)d_in[5];
    const float* W2   = (const float*)d_in[6];
    const float* b2   = (const float*)d_in[7];
    float* out = (float*)d_out;

    int n = in_sizes[0] / 216;               // B
    int grid = (n + 127) / 128;
    size_t smem = (size_t)SM_U64 * sizeof(u64t);

    cudaFuncSetAttribute(pose_kernel, cudaFuncAttributeMaxDynamicSharedMemorySize, (int)smem);
    pose_kernel<<<grid, 128, smem>>>(rots, jtrs, W0, b0, W1, b1, W2, b2, out, n);
}